// round 16
// baseline (speedup 1.0000x reference)
#include <cuda_runtime.h>
#include <cuda_fp16.h>
#include <math.h>
#include <stdint.h>

#define CB   512
#define CS   120
#define CD   216
#define CH   1024
#define CML  24

#define NCH_X 2
#define NT    32        // N tiles of 128 cols (4 j-octets x 4 gates x 8 j)
#define MT    64        // M tile per CTA
#define XSTR  256       // padded x-plane stride
#define NK16  80        // flat k16 steps (16 x + 64 h)

#define ABUF 16384
#define SMEM_STEP (6 * ABUF)            // 96KB, 2 CTAs/SM
#define SMEM_GX   (65536 + 3 * 32768)   // W 64KB + 3 A stages of 32KB = 160KB
#define GX_TPB 30                       // t-planes per prep_gx CTA (grid.z = 4)

// ---------------- device globals ----------------
__device__ __align__(16) uint4 g_Wfrag[(size_t)NT * 4 * NK16 * 64];   // 10.5MB
__device__ __align__(16) __half g_src[(size_t)CS * CB * XSTR];
__device__ __align__(16) __half g_xd[(size_t)CB * XSTR];
__device__ __align__(16) __half g_h[2][(size_t)CB * CH];
__device__ float g_c[(size_t)CB * CH];
__device__ float g_bias[4 * CH];
// gates_x fragments: [(t*256 + cta)*256 + tid] * 4 uint4  (fp16 pairs)  ~503MB
__device__ __align__(16) uint4 g_gx[(size_t)CS * 256 * 256 * 4];

// ---------------- helpers ----------------
__device__ __forceinline__ uint32_t smem_u32(const void* p) {
    uint32_t a;
    asm("{ .reg .u64 t; cvta.to.shared.u64 t, %1; cvt.u32.u64 %0, t; }" : "=r"(a) : "l"(p));
    return a;
}
__device__ __forceinline__ void ldsm4(uint32_t* r, uint32_t addr) {
    asm volatile("ldmatrix.sync.aligned.m8n8.x4.shared.b16 {%0,%1,%2,%3}, [%4];"
        : "=r"(r[0]), "=r"(r[1]), "=r"(r[2]), "=r"(r[3]) : "r"(addr));
}
__device__ __forceinline__ void mma_h(float* d, const uint32_t* a, uint32_t b0, uint32_t b1) {
    asm volatile("mma.sync.aligned.m16n8k16.row.col.f32.f16.f16.f32 "
        "{%0,%1,%2,%3}, {%4,%5,%6,%7}, {%8,%9}, {%0,%1,%2,%3};"
        : "+f"(d[0]), "+f"(d[1]), "+f"(d[2]), "+f"(d[3])
        : "r"(a[0]), "r"(a[1]), "r"(a[2]), "r"(a[3]), "r"(b0), "r"(b1));
}
#define CP16(dst, src) \
    asm volatile("cp.async.cg.shared.global [%0], [%1], 16;" :: "r"(dst), "l"(src))
#define CP_COMMIT() asm volatile("cp.async.commit_group;" ::: "memory")
#define CP_WAIT(n)  asm volatile("cp.async.wait_group %0;" :: "n"(n) : "memory")

__device__ __forceinline__ float sigf(float x) { return 1.0f / (1.0f + __expf(-x)); }
__device__ __forceinline__ uint32_t packh2(float a, float b) {
    return (uint32_t)__half_as_ushort(__float2half_rn(a)) |
           ((uint32_t)__half_as_ushort(__float2half_rn(b)) << 16);
}

// ---------------- init / precompute ----------------
__global__ void init_kernel(const float* __restrict__ b_ih, const float* __restrict__ b_hh) {
    int idx = blockIdx.x * blockDim.x + threadIdx.x;
    if (idx < CB * CH) {
        g_c[idx] = 0.0f;
        g_h[0][idx] = __float2half_rn(0.0f);
    }
    if (idx < CB * XSTR) g_xd[idx] = __float2half_rn(0.0f);
    if (idx < 4 * CH) g_bias[idx] = b_ih[idx] + b_hh[idx];
}

__global__ void src_split_kernel(const float* __restrict__ src) {
    size_t idx = (size_t)blockIdx.x * blockDim.x + threadIdx.x;
    if (idx >= (size_t)CS * CB * XSTR) return;
    int c = (int)(idx & (XSTR - 1));
    int r = (int)((idx >> 8) & (CB - 1));
    int t = (int)(idx >> 17);
    float v = (c < CD) ? src[((size_t)r * CS + t) * CD + c] : 0.0f;
    g_src[idx] = __float2half_rn(v);
}

// W -> B-fragment layout (fp16), gate-interleaved N packing (octet = gate).
__global__ void prep_w_kernel(const float* __restrict__ W_ih, const float* __restrict__ W_hh) {
    int s = blockIdx.x * blockDim.x + threadIdx.x;
    const int TOT = NT * 4 * NK16 * 128;
    if (s >= TOT) return;
    int nb   = s & 3;          // octet = GATE
    int lane = (s >> 2) & 31;
    int rest = s >> 7;
    int f  = rest % NK16; rest /= NK16;
    int wn = rest & 3;
    int nt = rest >> 2;

    int j = nt * 32 + wn * 8 + (lane >> 2);
    int R = nb * CH + j;
    int k0 = f * 16 + (lane & 3) * 2;

    float v[4];
    if (f < 16) {
        int ks[4] = {k0, k0 + 1, k0 + 8, k0 + 9};
#pragma unroll
        for (int q = 0; q < 4; ++q)
            v[q] = (ks[q] < CD) ? W_ih[(size_t)R * CD + ks[q]] : 0.0f;
    } else {
        const float* wr = W_hh + (size_t)R * CH + (k0 - 256);
        v[0] = wr[0]; v[1] = wr[1]; v[2] = wr[8]; v[3] = wr[9];
    }
    size_t dest = (((size_t)(nt * 4 + wn) * NK16 + f)) * 128 + lane * 4 + nb;
    ((uint2*)g_Wfrag)[dest] = make_uint2(packh2(v[0], v[1]), packh2(v[2], v[3]));
}

// ---------------- prep_gx: gates_x fragments for all 120 src planes ----------------
__global__ __launch_bounds__(256, 1)
void prep_gx_kernel()
{
    extern __shared__ char smem[];
    const uint32_t sb = smem_u32(smem);           // W region base
    const uint32_t sa = sb + 65536;               // A stages base
    const int tid = threadIdx.x;
    const int lane = tid & 31;
    const int w = tid >> 5;
    const int wm = w & 1;
    const int wn = w >> 1;
    const int nt = blockIdx.x;
    const int mb = blockIdx.y * MT;
    const int cta = blockIdx.y * NT + blockIdx.x;
    const int t0 = blockIdx.z * GX_TPB;

    // load W x-strips (f 0..15, all 4 wn) into smem: 4096 uint4
#pragma unroll
    for (int q = 0; q < 16; ++q) {
        int idx = tid + q * 256;
        int wnq = idx >> 10;
        int rem = idx & 1023;
        int fq = rem >> 6;
        int lq = rem & 63;
        ((uint4*)smem)[idx] = g_Wfrag[(((size_t)(nt * 4 + wnq)) * NK16 + fq) * 64 + lq];
    }

    // A mapping: per t, 2048 granules (2 sub-chunks x 1024), 8/thread
    int asub[8], arow[8], acg[8];
    uint32_t aoff[8];
#pragma unroll
    for (int it = 0; it < 8; ++it) {
        int idx = tid + it * 256;
        asub[it] = idx >> 10;
        int rem = idx & 1023;
        arow[it] = rem >> 4;
        acg[it]  = rem & 15;
        aoff[it] = (uint32_t)(asub[it] * 16384 + arow[it] * 256 + ((acg[it] ^ (arow[it] & 7)) << 4));
    }
    auto issue_A = [&](int t, uint32_t buf) {
        const __half* p0 = g_src + (size_t)t * CB * XSTR;
#pragma unroll
        for (int it = 0; it < 8; ++it) {
            const __half* sp = p0 + (size_t)(mb + arow[it]) * XSTR + asub[it] * 128 + acg[it] * 8;
            CP16(buf + aoff[it], sp);
        }
    };

    uint32_t abase[2]; int amask[2];
#pragma unroll
    for (int mg = 0; mg < 2; ++mg) {
        int rr = wm * 32 + mg * 16 + (lane & 15);
        abase[mg] = (uint32_t)(rr * 256);
        amask[mg] = rr & 7;
    }
    const int akc_half = lane >> 4;
    uint32_t ah[2][2][4];
    auto prefetch_A = [&](uint32_t buf, int fi, int b) {
        uint32_t g = (uint32_t)(2 * fi + akc_half);
#pragma unroll
        for (int mg = 0; mg < 2; ++mg)
            ldsm4(ah[b][mg], buf + abase[mg] + ((g ^ (uint32_t)amask[mg]) << 4));
    };

    const uint4* wsm = ((const uint4*)smem) + (size_t)wn * 16 * 64 + lane * 2;

    __syncthreads();   // W smem ready
    issue_A(t0, sa);                 CP_COMMIT();
    if (GX_TPB > 1) { issue_A(t0 + 1, sa + 32768); CP_COMMIT(); }

#pragma unroll 1
    for (int lt = 0; lt < GX_TPB; ++lt) {
        if (lt == GX_TPB - 1) { CP_WAIT(0); } else { CP_WAIT(1); }
        __syncthreads();
        if (lt + 2 < GX_TPB) issue_A(t0 + lt + 2, sa + (uint32_t)((lt + 2) % 3) * 32768);
        CP_COMMIT();

        const uint32_t stage = sa + (uint32_t)(lt % 3) * 32768;
        float acc[2][4][4];
#pragma unroll
        for (int mg = 0; mg < 2; ++mg)
#pragma unroll
            for (int nb = 0; nb < 4; ++nb)
#pragma unroll
                for (int e = 0; e < 4; ++e) acc[mg][nb][e] = 0.0f;

        uint4 wc0 = wsm[0], wc1 = wsm[1];
        prefetch_A(stage, 0, 0);
        int cur = 0;
#pragma unroll
        for (int fi = 0; fi < 16; ++fi) {
            uint4 wn0, wn1;
            if (fi < 15) {
                const uint4* np = wsm + (size_t)(fi + 1) * 64;
                wn0 = np[0]; wn1 = np[1];
                const uint32_t buf = stage + (uint32_t)(((fi + 1) >> 3) - (fi >> 3)) * 0;
                prefetch_A(stage + (uint32_t)(((fi + 1) >> 3)) * 16384 - (uint32_t)((fi + 1) >> 3) * 0,
                           (fi + 1) & 7, cur ^ 1);
                (void)buf;
            }
            uint32_t b0[4] = {wc0.x, wc0.z, wc1.x, wc1.z};
            uint32_t b1[4] = {wc0.y, wc0.w, wc1.y, wc1.w};
#pragma unroll
            for (int mg = 0; mg < 2; ++mg)
#pragma unroll
                for (int nb = 0; nb < 4; ++nb)
                    mma_h(acc[mg][nb], ah[cur][mg], b0[nb], b1[nb]);
            if (fi < 15) { wc0 = wn0; wc1 = wn1; }
            cur ^= 1;
        }

        // pack & store fragments (fp16 pairs), coalesced
        uint4 os[4];
#pragma unroll
        for (int mg = 0; mg < 2; ++mg)
#pragma unroll
            for (int eh = 0; eh < 2; ++eh) {
                uint32_t* oc = (uint32_t*)&os[mg * 2 + eh];
#pragma unroll
                for (int nb = 0; nb < 4; ++nb)
                    oc[nb] = packh2(acc[mg][nb][eh * 2], acc[mg][nb][eh * 2 + 1]);
            }
        uint4* gp = g_gx + (((size_t)(t0 + lt) * 256 + cta) * 256 + tid) * 4;
        gp[0] = os[0]; gp[1] = os[1]; gp[2] = os[2]; gp[3] = os[3];
    }
}

// ---------------- fused LSTM step (templated on gx availability) ----------------
template<bool HASGX>
__global__ __launch_bounds__(256, 2)
void lstm_step_t(int use_xd, int tpl, int rd, int wr)
{
    extern __shared__ char smem[];
    const uint32_t sb = smem_u32(smem);
    const int tid = threadIdx.x;
    const int lane = tid & 31;
    const int w = tid >> 5;
    const int wm = w & 1;
    const int wn = w >> 1;
    const int nt = blockIdx.x;
    const int mb = blockIdx.y * MT;
    const int cta = blockIdx.y * NT + blockIdx.x;

    const __half* xp = use_xd ? g_xd : (g_src + (size_t)tpl * CB * XSTR);
    const __half* hp = g_h[rd];

    constexpr int NPAIR = HASGX ? 4 : 5;
    constexpr int F0    = HASGX ? 16 : 0;

    int ar[4], acg[4];
    uint32_t aoff[4];
#pragma unroll
    for (int it = 0; it < 4; ++it) {
        int idx = tid + it * 256;
        ar[it]  = idx >> 4;
        acg[it] = idx & 15;
        aoff[it] = (uint32_t)(ar[it] * 256 + ((acg[it] ^ (ar[it] & 7)) << 4));
    }

    auto issue_chunk = [&](int ch, uint32_t buf) {
        const __half* p0;
        int stride, koff;
        if (HASGX)            { p0 = hp; stride = CH;   koff = ch * 128; }
        else if (ch < NCH_X)  { p0 = xp; stride = XSTR; koff = ch * 128; }
        else                  { p0 = hp; stride = CH;   koff = (ch - NCH_X) * 128; }
#pragma unroll
        for (int it = 0; it < 4; ++it) {
            const __half* sp = p0 + (size_t)(mb + ar[it]) * stride + koff + acg[it] * 8;
            CP16(buf + aoff[it], sp);
        }
    };

    uint32_t abase[2]; int amask[2];
#pragma unroll
    for (int mg = 0; mg < 2; ++mg) {
        int rr = wm * 32 + mg * 16 + (lane & 15);
        abase[mg] = (uint32_t)(rr * 256);
        amask[mg] = rr & 7;
    }
    const int akc_half = lane >> 4;
    uint32_t ah[2][2][4];
    auto prefetch_A = [&](uint32_t buf, int fi, int b) {
        uint32_t g = (uint32_t)(2 * fi + akc_half);
#pragma unroll
        for (int mg = 0; mg < 2; ++mg)
            ldsm4(ah[b][mg], buf + abase[mg] + ((g ^ (uint32_t)amask[mg]) << 4));
    };

    const uint4* wbase = g_Wfrag + ((size_t)(nt * 4 + wn) * NK16) * 64 + lane * 2;

    float acc[2][4][4];
#pragma unroll
    for (int mg = 0; mg < 2; ++mg)
#pragma unroll
        for (int nb = 0; nb < 4; ++nb)
#pragma unroll
            for (int e = 0; e < 4; ++e) acc[mg][nb][e] = 0.0f;

    issue_chunk(0, sb);
    issue_chunk(1, sb + ABUF);
    CP_COMMIT();
    issue_chunk(2, sb + 2 * ABUF);
    issue_chunk(3, sb + 3 * ABUF);
    CP_COMMIT();

    uint4 wr0[4], wr1[4];
#pragma unroll
    for (int s = 0; s < 3; ++s) {
        const uint4* np = wbase + (size_t)(F0 + s) * 64;
        wr0[s] = __ldg(np); wr1[s] = __ldg(np + 1);
    }

#pragma unroll 1
    for (int pr = 0; pr < NPAIR; ++pr) {
        if (pr == NPAIR - 1) { CP_WAIT(0); } else { CP_WAIT(1); }
        __syncthreads();
        if (pr + 2 < NPAIR) {
            int c0 = 2 * (pr + 2);
            issue_chunk(c0,     sb + (uint32_t)(c0 % 6) * ABUF);
            issue_chunk(c0 + 1, sb + (uint32_t)((c0 + 1) % 6) * ABUF);
        }
        CP_COMMIT();

        const uint32_t buf0 = sb + (uint32_t)((2 * pr) % 6) * ABUF;
        const uint32_t buf1 = sb + (uint32_t)((2 * pr + 1) % 6) * ABUF;

        prefetch_A(buf0, 0, 0);
        int cur = 0;
#pragma unroll
        for (int fi = 0; fi < 16; ++fi) {
            const int f = F0 + pr * 16 + fi;
            if (f + 3 < NK16) {
                const uint4* np = wbase + (size_t)(f + 3) * 64;
                wr0[(fi + 3) & 3] = __ldg(np);
                wr1[(fi + 3) & 3] = __ldg(np + 1);
            }
            if (fi < 15) {
                const int nfi = fi + 1;
                prefetch_A((nfi < 8) ? buf0 : buf1, nfi & 7, cur ^ 1);
            }
            const int ws = fi & 3;
            uint32_t b0[4] = {wr0[ws].x, wr0[ws].z, wr1[ws].x, wr1[ws].z};
            uint32_t b1[4] = {wr0[ws].y, wr0[ws].w, wr1[ws].y, wr1[ws].w};
#pragma unroll
            for (int mg = 0; mg < 2; ++mg)
#pragma unroll
                for (int nb = 0; nb < 4; ++nb)
                    mma_h(acc[mg][nb], ah[cur][mg], b0[nb], b1[nb]);
            cur ^= 1;
        }
    }

    // add precomputed gates_x
    if (HASGX) {
        const uint4* gp = g_gx + (((size_t)tpl * 256 + cta) * 256 + tid) * 4;
        uint4 os[4];
        os[0] = __ldg(gp); os[1] = __ldg(gp + 1); os[2] = __ldg(gp + 2); os[3] = __ldg(gp + 3);
#pragma unroll
        for (int mg = 0; mg < 2; ++mg)
#pragma unroll
            for (int eh = 0; eh < 2; ++eh) {
                const uint32_t* oc = (const uint32_t*)&os[mg * 2 + eh];
#pragma unroll
                for (int nb = 0; nb < 4; ++nb) {
                    float2 v = __half22float2(*(const __half2*)&oc[nb]);
                    acc[mg][nb][eh * 2 + 0] += v.x;
                    acc[mg][nb][eh * 2 + 1] += v.y;
                }
            }
    }

    // in-register cell update
    {
        const int jbase = nt * 32 + wn * 8 + (lane & 3) * 2;
        float bias2[4][2];
#pragma unroll
        for (int g = 0; g < 4; ++g) {
            bias2[g][0] = g_bias[g * CH + jbase];
            bias2[g][1] = g_bias[g * CH + jbase + 1];
        }
        __half* hw = g_h[wr];
#pragma unroll
        for (int mg = 0; mg < 2; ++mg) {
#pragma unroll
            for (int half = 0; half < 2; ++half) {
                int row = mb + wm * 32 + mg * 16 + (lane >> 2) + half * 8;
                size_t off = (size_t)row * CH + jbase;
                float2 cc = *(const float2*)(g_c + off);
                float cold[2] = {cc.x, cc.y};
                float hn[2];
#pragma unroll
                for (int jl = 0; jl < 2; ++jl) {
                    int e = half * 2 + jl;
                    float gi = acc[mg][0][e] + bias2[0][jl];
                    float gf = acc[mg][1][e] + bias2[1][jl];
                    float gg = acc[mg][2][e] + bias2[2][jl];
                    float go = acc[mg][3][e] + bias2[3][jl];
                    float cn = sigf(gf) * cold[jl] + sigf(gi) * tanhf(gg);
                    hn[jl] = sigf(go) * tanhf(cn);
                    cold[jl] = cn;
                }
                *(float2*)(g_c + off) = make_float2(cold[0], cold[1]);
                *(uint32_t*)(hw + off) = packh2(hn[0], hn[1]);
            }
        }
    }
}

// ---------------- decoder projection ----------------
__global__ __launch_bounds__(256)
void proj_kernel(int hbuf,
                 const float* __restrict__ W_out,
                 const float* __restrict__ b_out,
                 float* __restrict__ outp)
{
    int lane = threadIdx.x & 31;
    int w = threadIdx.x >> 5;
    int d = blockIdx.x * 8 + w;
    int r0 = blockIdx.y * 8;
    const __half* hp = g_h[hbuf];
    int k0 = lane * 32;

    float wv[32];
    {
        const float4* wp = (const float4*)(W_out + (size_t)d * CH + k0);
#pragma unroll
        for (int q = 0; q < 8; ++q) {
            float4 f = wp[q];
            wv[q * 4 + 0] = f.x; wv[q * 4 + 1] = f.y; wv[q * 4 + 2] = f.z; wv[q * 4 + 3] = f.w;
        }
    }
    float acc[8];
#pragma unroll
    for (int r = 0; r < 8; ++r) {
        const uint4* hq = (const uint4*)(hp + (size_t)(r0 + r) * CH + k0);
        float s = 0.0f;
#pragma unroll
        for (int q = 0; q < 4; ++q) {
            uint4 hv = hq[q];
            const __half2* h2 = (const __half2*)&hv;
#pragma unroll
            for (int e = 0; e < 4; ++e) {
                float2 a = __half22float2(h2[e]);
                int kk = q * 8 + e * 2;
                s += a.x * wv[kk] + a.y * wv[kk + 1];
            }
        }
        acc[r] = s;
    }
#pragma unroll
    for (int r = 0; r < 8; ++r) {
#pragma unroll
        for (int off = 16; off > 0; off >>= 1)
            acc[r] += __shfl_xor_sync(0xFFFFFFFFu, acc[r], off);
    }
    if (lane == 0) {
        float bo = b_out[d];
#pragma unroll
        for (int r = 0; r < 8; ++r) {
            float y = acc[r] + bo;
            int row = r0 + r;
            outp[(size_t)row * CML * CD + d] = y;
            g_xd[(size_t)row * XSTR + d] = __float2half_rn(y);
        }
    }
}

extern "C" void kernel_launch(void* const* d_in, const int* in_sizes, int n_in,
                              void* d_out, int out_size)
{
    (void)in_sizes; (void)n_in; (void)out_size;
    const float* src   = (const float*)d_in[0];
    const float* W_ih  = (const float*)d_in[1];
    const float* W_hh  = (const float*)d_in[2];
    const float* b_ih  = (const float*)d_in[3];
    const float* b_hh  = (const float*)d_in[4];
    const float* W_out = (const float*)d_in[5];
    const float* b_out = (const float*)d_in[6];
    float* out = (float*)d_out;

    static int once = 0;
    if (!once) {
        cudaFuncSetAttribute(lstm_step_t<true>,  cudaFuncAttributeMaxDynamicSharedMemorySize, SMEM_STEP);
        cudaFuncSetAttribute(lstm_step_t<false>, cudaFuncAttributeMaxDynamicSharedMemorySize, SMEM_STEP);
        cudaFuncSetAttribute(prep_gx_kernel,     cudaFuncAttributeMaxDynamicSharedMemorySize, SMEM_GX);
        once = 1;
    }

    init_kernel<<<(CB * CH + 255) / 256, 256>>>(b_ih, b_hh);
    {
        size_t tot = (size_t)CS * CB * XSTR;
        src_split_kernel<<<(unsigned)((tot + 255) / 256), 256>>>(src);
    }
    {
        int tot = NT * 4 * NK16 * 128;
        prep_w_kernel<<<(tot + 255) / 256, 256>>>(W_ih, W_hh);
    }
    prep_gx_kernel<<<dim3(NT, CB / MT, CS / GX_TPB), 256, SMEM_GX>>>();

    dim3 sgrid(NT, CB / MT);   // 32 x 8 = 256 CTAs
    dim3 pgrid(27, CB / 8);    // 27 x 64

    int p = 0;
    for (int t = 0; t < CS; ++t) {
        lstm_step_t<true><<<sgrid, 256, SMEM_STEP>>>(0, t, p, p ^ 1);
        p ^= 1;
    }
    for (int s = 0; s < CML; ++s) {
        if (s == 0) lstm_step_t<true><<<sgrid, 256, SMEM_STEP>>>(0, CS - 1, p, p ^ 1);
        else        lstm_step_t<false><<<sgrid, 256, SMEM_STEP>>>(1, 0, p, p ^ 1);
        proj_kernel<<<pgrid, 256>>>(p ^ 1, W_out, b_out, out + (size_t)s * CD);
        p ^= 1;
    }
}

// round 17
// speedup vs baseline: 1.1160x; 1.1160x over previous
#include <cuda_runtime.h>
#include <cuda_fp16.h>
#include <math.h>
#include <stdint.h>

#define CB   512
#define CS   120
#define CD   216
#define CH   1024
#define CML  24

#define NCH   10
#define NCH_X 2
#define NT    32
#define MT    64
#define XSTR  256
#define NK16  80

#define ABUF 16384
#define SMEM_STEP (6 * ABUF)   // 96KB, 2 CTAs/SM

// ---------------- device globals ----------------
__device__ __align__(16) uint4 g_Wfrag[(size_t)NT * 4 * NK16 * 64];   // 10.5MB
__device__ __align__(16) __half g_src[(size_t)CS * CB * XSTR];
__device__ __align__(16) __half g_xd[(size_t)CB * XSTR];
__device__ __align__(16) __half g_h[2][(size_t)CB * CH];
__device__ __align__(16) __half g_wout16[(size_t)CD * CH];
__device__ float g_c[(size_t)CB * CH];
__device__ float g_bias[4 * CH];

// ---------------- helpers ----------------
__device__ __forceinline__ uint32_t smem_u32(const void* p) {
    uint32_t a;
    asm("{ .reg .u64 t; cvta.to.shared.u64 t, %1; cvt.u32.u64 %0, t; }" : "=r"(a) : "l"(p));
    return a;
}
__device__ __forceinline__ void ldsm4(uint32_t* r, uint32_t addr) {
    asm volatile("ldmatrix.sync.aligned.m8n8.x4.shared.b16 {%0,%1,%2,%3}, [%4];"
        : "=r"(r[0]), "=r"(r[1]), "=r"(r[2]), "=r"(r[3]) : "r"(addr));
}
__device__ __forceinline__ void mma_h(float* d, const uint32_t* a, uint32_t b0, uint32_t b1) {
    asm volatile("mma.sync.aligned.m16n8k16.row.col.f32.f16.f16.f32 "
        "{%0,%1,%2,%3}, {%4,%5,%6,%7}, {%8,%9}, {%0,%1,%2,%3};"
        : "+f"(d[0]), "+f"(d[1]), "+f"(d[2]), "+f"(d[3])
        : "r"(a[0]), "r"(a[1]), "r"(a[2]), "r"(a[3]), "r"(b0), "r"(b1));
}
#define CP16(dst, src) \
    asm volatile("cp.async.cg.shared.global [%0], [%1], 16;" :: "r"(dst), "l"(src))
#define CP_COMMIT() asm volatile("cp.async.commit_group;" ::: "memory")
#define CP_WAIT(n)  asm volatile("cp.async.wait_group %0;" :: "n"(n) : "memory")

__device__ __forceinline__ float sigf(float x) { return 1.0f / (1.0f + __expf(-x)); }
__device__ __forceinline__ uint32_t packh2(float a, float b) {
    return (uint32_t)__half_as_ushort(__float2half_rn(a)) |
           ((uint32_t)__half_as_ushort(__float2half_rn(b)) << 16);
}

// ---------------- init / precompute ----------------
__global__ void init_kernel(const float* __restrict__ b_ih, const float* __restrict__ b_hh,
                            const float* __restrict__ W_out) {
    int idx = blockIdx.x * blockDim.x + threadIdx.x;
    if (idx < CB * CH) {
        g_c[idx] = 0.0f;
        g_h[0][idx] = __float2half_rn(0.0f);
    }
    if (idx < CB * XSTR) g_xd[idx] = __float2half_rn(0.0f);
    if (idx < 4 * CH) g_bias[idx] = b_ih[idx] + b_hh[idx];
    if (idx < CD * CH) g_wout16[idx] = __float2half_rn(W_out[idx]);
}

__global__ void src_split_kernel(const float* __restrict__ src) {
    size_t idx = (size_t)blockIdx.x * blockDim.x + threadIdx.x;
    if (idx >= (size_t)CS * CB * XSTR) return;
    int c = (int)(idx & (XSTR - 1));
    int r = (int)((idx >> 8) & (CB - 1));
    int t = (int)(idx >> 17);
    float v = (c < CD) ? src[((size_t)r * CS + t) * CD + c] : 0.0f;
    g_src[idx] = __float2half_rn(v);
}

// W -> B-fragment layout (fp16), gate-interleaved N packing (octet = gate).
__global__ void prep_w_kernel(const float* __restrict__ W_ih, const float* __restrict__ W_hh) {
    int s = blockIdx.x * blockDim.x + threadIdx.x;
    const int TOT = NT * 4 * NK16 * 128;
    if (s >= TOT) return;
    int nb   = s & 3;          // octet = GATE
    int lane = (s >> 2) & 31;
    int rest = s >> 7;
    int f  = rest % NK16; rest /= NK16;
    int wn = rest & 3;
    int nt = rest >> 2;

    int j = nt * 32 + wn * 8 + (lane >> 2);
    int R = nb * CH + j;
    int k0 = f * 16 + (lane & 3) * 2;

    float v[4];
    if (f < 16) {
        int ks[4] = {k0, k0 + 1, k0 + 8, k0 + 9};
#pragma unroll
        for (int q = 0; q < 4; ++q)
            v[q] = (ks[q] < CD) ? W_ih[(size_t)R * CD + ks[q]] : 0.0f;
    } else {
        const float* wr = W_hh + (size_t)R * CH + (k0 - 256);
        v[0] = wr[0]; v[1] = wr[1]; v[2] = wr[8]; v[3] = wr[9];
    }
    size_t dest = (((size_t)(nt * 4 + wn) * NK16 + f)) * 128 + lane * 4 + nb;
    ((uint2*)g_Wfrag)[dest] = make_uint2(packh2(v[0], v[1]), packh2(v[2], v[3]));
}

// ---------------- fused LSTM step: 6-stage ring, pair-granularity barriers ----------------
__global__ __launch_bounds__(256, 2)
void lstm_step(int use_xd, int t, int rd, int wr)
{
    extern __shared__ char smem[];
    const uint32_t sb = smem_u32(smem);
    const int tid = threadIdx.x;
    const int lane = tid & 31;
    const int w = tid >> 5;
    const int wm = w & 1;
    const int wn = w >> 1;
    const int nt = blockIdx.x;
    const int mb = blockIdx.y * MT;

    const __half* xp = use_xd ? g_xd : (g_src + (size_t)t * CB * XSTR);
    const __half* hp = g_h[rd];

    int ar[4], acg[4];
    uint32_t aoff[4];
#pragma unroll
    for (int it = 0; it < 4; ++it) {
        int idx = tid + it * 256;
        ar[it]  = idx >> 4;
        acg[it] = idx & 15;
        aoff[it] = (uint32_t)(ar[it] * 256 + ((acg[it] ^ (ar[it] & 7)) << 4));
    }

    auto issue_chunk = [&](int ch, uint32_t buf) {
        const __half* p0;
        int stride, koff;
        if (ch < NCH_X) { p0 = xp; stride = XSTR; koff = ch * 128; }
        else            { p0 = hp; stride = CH;   koff = (ch - NCH_X) * 128; }
#pragma unroll
        for (int it = 0; it < 4; ++it) {
            const __half* sp = p0 + (size_t)(mb + ar[it]) * stride + koff + acg[it] * 8;
            CP16(buf + aoff[it], sp);
        }
    };

    uint32_t abase[2]; int amask[2];
#pragma unroll
    for (int mg = 0; mg < 2; ++mg) {
        int rr = wm * 32 + mg * 16 + (lane & 15);
        abase[mg] = (uint32_t)(rr * 256);
        amask[mg] = rr & 7;
    }
    const int akc_half = lane >> 4;

    uint32_t ah[2][2][4];
    auto prefetch_A = [&](uint32_t buf, int fi, int b) {
        uint32_t g = (uint32_t)(2 * fi + akc_half);
#pragma unroll
        for (int mg = 0; mg < 2; ++mg)
            ldsm4(ah[b][mg], buf + abase[mg] + ((g ^ (uint32_t)amask[mg]) << 4));
    };

    const uint4* wbase = g_Wfrag + ((size_t)(nt * 4 + wn) * NK16) * 64 + lane * 2;

    float acc[2][4][4];
#pragma unroll
    for (int mg = 0; mg < 2; ++mg)
#pragma unroll
        for (int nb = 0; nb < 4; ++nb)
#pragma unroll
            for (int e = 0; e < 4; ++e) acc[mg][nb][e] = 0.0f;

    issue_chunk(0, sb);
    issue_chunk(1, sb + ABUF);
    CP_COMMIT();
    issue_chunk(2, sb + 2 * ABUF);
    issue_chunk(3, sb + 3 * ABUF);
    CP_COMMIT();

    uint4 wr0[4], wr1[4];
#pragma unroll
    for (int s = 0; s < 3; ++s) {
        const uint4* np = wbase + (size_t)s * 64;
        wr0[s] = __ldg(np); wr1[s] = __ldg(np + 1);
    }

#pragma unroll 1
    for (int pr = 0; pr < 5; ++pr) {
        if (pr == 4) { CP_WAIT(0); } else { CP_WAIT(1); }
        __syncthreads();
        if (pr + 2 < 5) {
            int c0 = 2 * (pr + 2);
            issue_chunk(c0,     sb + (uint32_t)(c0 % 6) * ABUF);
            issue_chunk(c0 + 1, sb + (uint32_t)((c0 + 1) % 6) * ABUF);
        }
        CP_COMMIT();

        const uint32_t buf0 = sb + (uint32_t)((2 * pr) % 6) * ABUF;
        const uint32_t buf1 = sb + (uint32_t)((2 * pr + 1) % 6) * ABUF;

        prefetch_A(buf0, 0, 0);
        int cur = 0;
#pragma unroll
        for (int fi = 0; fi < 16; ++fi) {
            const int f = pr * 16 + fi;
            if (f + 3 < NK16) {
                const uint4* np = wbase + (size_t)(f + 3) * 64;
                wr0[(fi + 3) & 3] = __ldg(np);
                wr1[(fi + 3) & 3] = __ldg(np + 1);
            }
            if (fi < 15) {
                const int nfi = fi + 1;
                prefetch_A((nfi < 8) ? buf0 : buf1, nfi & 7, cur ^ 1);
            }

            const int ws = fi & 3;
            uint32_t b0[4] = {wr0[ws].x, wr0[ws].z, wr1[ws].x, wr1[ws].z};
            uint32_t b1[4] = {wr0[ws].y, wr0[ws].w, wr1[ws].y, wr1[ws].w};
#pragma unroll
            for (int mg = 0; mg < 2; ++mg)
#pragma unroll
                for (int nb = 0; nb < 4; ++nb)
                    mma_h(acc[mg][nb], ah[cur][mg], b0[nb], b1[nb]);
            cur ^= 1;
        }
    }

    // in-register cell update
    {
        const int jbase = nt * 32 + wn * 8 + (lane & 3) * 2;
        float bias2[4][2];
#pragma unroll
        for (int g = 0; g < 4; ++g) {
            bias2[g][0] = g_bias[g * CH + jbase];
            bias2[g][1] = g_bias[g * CH + jbase + 1];
        }
        __half* hw = g_h[wr];
#pragma unroll
        for (int mg = 0; mg < 2; ++mg) {
#pragma unroll
            for (int half = 0; half < 2; ++half) {
                int row = mb + wm * 32 + mg * 16 + (lane >> 2) + half * 8;
                size_t off = (size_t)row * CH + jbase;
                float2 cc = *(const float2*)(g_c + off);
                float cold[2] = {cc.x, cc.y};
                float hn[2];
#pragma unroll
                for (int jl = 0; jl < 2; ++jl) {
                    int e = half * 2 + jl;
                    float gi = acc[mg][0][e] + bias2[0][jl];
                    float gf = acc[mg][1][e] + bias2[1][jl];
                    float gg = acc[mg][2][e] + bias2[2][jl];
                    float go = acc[mg][3][e] + bias2[3][jl];
                    float cn = sigf(gf) * cold[jl] + sigf(gi) * tanhf(gg);
                    hn[jl] = sigf(go) * tanhf(cn);
                    cold[jl] = cn;
                }
                *(float2*)(g_c + off) = make_float2(cold[0], cold[1]);
                *(uint32_t*)(hw + off) = packh2(hn[0], hn[1]);
            }
        }
    }
}

// ---------------- decoder projection: fp16 W_out, 16 rows/warp ----------------
__global__ __launch_bounds__(256)
void proj_kernel(int hbuf,
                 const float* __restrict__ b_out,
                 float* __restrict__ outp)
{
    int lane = threadIdx.x & 31;
    int w = threadIdx.x >> 5;
    int d = blockIdx.x * 8 + w;          // 27 x 8 = 216
    int r0 = blockIdx.y * 16;            // 32 x 16 = 512
    const __half* hp = g_h[hbuf];
    int k0 = lane * 32;

    // W_out row d, lane's 32 k's (fp16 -> fp32)
    float wv[32];
    {
        const uint4* wp = (const uint4*)(g_wout16 + (size_t)d * CH + k0);
#pragma unroll
        for (int q = 0; q < 4; ++q) {
            uint4 wq = __ldg(wp + q);
            const __half2* w2 = (const __half2*)&wq;
#pragma unroll
            for (int e = 0; e < 4; ++e) {
                float2 f = __half22float2(w2[e]);
                wv[q * 8 + e * 2]     = f.x;
                wv[q * 8 + e * 2 + 1] = f.y;
            }
        }
    }
    float acc[16];
#pragma unroll
    for (int r = 0; r < 16; ++r) {
        const uint4* hq = (const uint4*)(hp + (size_t)(r0 + r) * CH + k0);
        float s = 0.0f;
#pragma unroll
        for (int q = 0; q < 4; ++q) {
            uint4 hv = __ldg(hq + q);
            const __half2* h2 = (const __half2*)&hv;
#pragma unroll
            for (int e = 0; e < 4; ++e) {
                float2 a = __half22float2(h2[e]);
                int kk = q * 8 + e * 2;
                s += a.x * wv[kk] + a.y * wv[kk + 1];
            }
        }
        acc[r] = s;
    }
#pragma unroll
    for (int r = 0; r < 16; ++r) {
#pragma unroll
        for (int off = 16; off > 0; off >>= 1)
            acc[r] += __shfl_xor_sync(0xFFFFFFFFu, acc[r], off);
    }
    if (lane == 0) {
        float bo = b_out[d];
#pragma unroll
        for (int r = 0; r < 16; ++r) {
            float y = acc[r] + bo;
            int row = r0 + r;
            outp[(size_t)row * CML * CD + d] = y;
            g_xd[(size_t)row * XSTR + d] = __float2half_rn(y);
        }
    }
}

extern "C" void kernel_launch(void* const* d_in, const int* in_sizes, int n_in,
                              void* d_out, int out_size)
{
    (void)in_sizes; (void)n_in; (void)out_size;
    const float* src   = (const float*)d_in[0];
    const float* W_ih  = (const float*)d_in[1];
    const float* W_hh  = (const float*)d_in[2];
    const float* b_ih  = (const float*)d_in[3];
    const float* b_hh  = (const float*)d_in[4];
    const float* W_out = (const float*)d_in[5];
    const float* b_out = (const float*)d_in[6];
    float* out = (float*)d_out;

    static int once = 0;
    if (!once) {
        cudaFuncSetAttribute(lstm_step, cudaFuncAttributeMaxDynamicSharedMemorySize, SMEM_STEP);
        once = 1;
    }

    init_kernel<<<(CB * CH + 255) / 256, 256>>>(b_ih, b_hh, W_out);
    {
        size_t tot = (size_t)CS * CB * XSTR;
        src_split_kernel<<<(unsigned)((tot + 255) / 256), 256>>>(src);
    }
    {
        int tot = NT * 4 * NK16 * 128;
        prep_w_kernel<<<(tot + 255) / 256, 256>>>(W_ih, W_hh);
    }

    dim3 sgrid(NT, CB / MT);   // 32 x 8 = 256 CTAs
    dim3 pgrid(27, CB / 16);   // 27 x 32

    int p = 0;
    for (int t = 0; t < CS; ++t) {
        lstm_step<<<sgrid, 256, SMEM_STEP>>>(0, t, p, p ^ 1);
        p ^= 1;
    }
    for (int s = 0; s < CML; ++s) {
        if (s == 0) lstm_step<<<sgrid, 256, SMEM_STEP>>>(0, CS - 1, p, p ^ 1);
        else        lstm_step<<<sgrid, 256, SMEM_STEP>>>(1, 0, p, p ^ 1);
        proj_kernel<<<pgrid, 256>>>(p ^ 1, b_out, out + (size_t)s * CD);
        p ^= 1;
    }
}